// round 12
// baseline (speedup 1.0000x reference)
#include <cuda_runtime.h>

#define NBATCH 4096
#define TT     2048
#define SDIM   5
#define CHUNK  16                // delta steps staged per smem refill
#define NCHUNK (TT / CHUNK)

typedef unsigned long long ull;

// ---- packed f32x2 helpers (sm_100+/sm_103a) ----
__device__ __forceinline__ ull pack2(float lo, float hi) {
    ull r; asm("mov.b64 %0, {%1, %2};" : "=l"(r) : "f"(lo), "f"(hi)); return r;
}
__device__ __forceinline__ void unpack2(ull a, float& lo, float& hi) {
    asm("mov.b64 {%0, %1}, %2;" : "=f"(lo), "=f"(hi) : "l"(a));
}
__device__ __forceinline__ ull mul2(ull a, ull b) {
    ull d; asm("mul.rn.f32x2 %0, %1, %2;" : "=l"(d) : "l"(a), "l"(b)); return d;
}
__device__ __forceinline__ ull add2(ull a, ull b) {
    ull d; asm("add.rn.f32x2 %0, %1, %2;" : "=l"(d) : "l"(a), "l"(b)); return d;
}
__device__ __forceinline__ void fma2(ull& d, ull a, ull b) {
    asm("fma.rn.f32x2 %0, %1, %2, %0;" : "+l"(d) : "l"(a), "l"(b));
}

#define SC 2.885390081777926815f   // 2*log2(e): folded into W2/b2 only

__device__ __forceinline__ float tanh_hw(float x) {       // stage-1 (MUFU.TANH)
    float y; asm("tanh.approx.f32 %0, %1;" : "=f"(y) : "f"(x));
    return y;
}
__device__ __forceinline__ float tanh_pre(float y) {      // stage-2 (precise, prescaled)
    float e, r;
    asm("ex2.approx.f32 %0, %1;" : "=f"(e) : "f"(y));
    asm("rcp.approx.f32 %0, %1;" : "=f"(r) : "f"(e + 1.0f));
    return fmaf(-2.0f, r, 1.0f);
}

#define SHF16(v, src) __shfl_sync(0xffffffffu, (v), (src), 16)
#define SHFX(v, m)    __shfl_xor_sync(0xffffffffu, (v), (m))

__global__ __launch_bounds__(32)   // 1 warp per block; regs effectively uncapped
void msc_seq_kernel(const float* __restrict__ delta,
                    const float* __restrict__ state0,
                    const float* __restrict__ W1, const float* __restrict__ b1,
                    const float* __restrict__ W2, const float* __restrict__ b2,
                    const float* __restrict__ W3, const float* __restrict__ b3,
                    float* __restrict__ out)
{
    // h1 lines: [seq][half][48]; halves 192B apart -> +16 banks, conflict-free
    __shared__ __align__(16) float sh1[2][2][48];
    // staged delta: [seq][half][80] (float4/step); halves 320B apart -> +16 banks
    __shared__ __align__(16) float shd[2][2][80];

    const int lane = threadIdx.x;        // 32-thread block = one warp
    const int h    = lane >> 4;          // which half (batch group)
    const int hl   = lane & 15;          // lane within half
    const int bA   = blockIdx.x * 4 + h * 2;   // two interleaved batches per half
    const int bB   = bA + 1;

    const int j0 = 2 * hl, j1 = 2 * hl + 1;    // ADJACENT owned channels -> STS.64

    // ---- weights in registers (SHARED across both interleaved sequences) ----
    float w1a[8], w1b[8];
#pragma unroll
    for (int i = 0; i < 8; i++) {
        w1a[i] = W1[i * 32 + j0];
        w1b[i] = W1[i * 32 + j1];
    }
    ull w2p[16], w2q[16];
#pragma unroll
    for (int p = 0; p < 16; p++) {
        w2p[p] = pack2(W2[(2 * p) * 32 + j0] * SC, W2[(2 * p + 1) * 32 + j0] * SC);
        w2q[p] = pack2(W2[(2 * p) * 32 + j1] * SC, W2[(2 * p + 1) * 32 + j1] * SC);
    }
    float w3a[5], w3b[5];
#pragma unroll
    for (int k = 0; k < 5; k++) {
        w3a[k] = W3[j0 * SDIM + k];
        w3b[k] = W3[j1 * SDIM + k];
    }
    const float b1a = b1[j0], b1c = b1[j1];
    const float b2a = b2[j0] * SC, b2c = b2[j1] * SC;

    // ---- slot mapping (16-lane merge tree) ----
    const int t3 = (hl >> 3) & 1, t2 = (hl >> 2) & 1, t1 = (hl >> 1) & 1;
    const int vidx = t1 ? 4 : (t2 ? (t3 ? 3 : 2) : (t3 ? 1 : 0));
    const bool wr  = (hl == 0) | (hl == 8) | (hl == 4) | (hl == 12) | (hl == 2);
    const float b3v = b3[vidx];

    float stvA = state0[bA * SDIM + vidx];
    float stvB = state0[bB * SDIM + vidx];

    const float* dApt = delta + (size_t)bA * (TT * 3);
    const float* dBpt = delta + (size_t)bB * (TT * 3);
    float* oA = out + (size_t)bA * (TT * SDIM) + vidx;
    float* oB = out + (size_t)bB * (TT * SDIM) + vidx;

    float rA0 = dApt[hl * 3 + 0], rA1 = dApt[hl * 3 + 1], rA2 = dApt[hl * 3 + 2];
    float rB0 = dBpt[hl * 3 + 0], rB1 = dBpt[hl * 3 + 1], rB2 = dBpt[hl * 3 + 2];

    float* lineA = &sh1[0][h][0];
    float* lineB = &sh1[1][h][0];
    const ulonglong2* hpA = (const ulonglong2*)lineA;
    const ulonglong2* hpB = (const ulonglong2*)lineB;

    for (int c = 0; c < NCHUNK; c++) {
        __syncwarp();
        *(float4*)(&shd[0][h][hl * 4]) = make_float4(rA0, rA1, rA2, 0.f);
        *(float4*)(&shd[1][h][hl * 4]) = make_float4(rB0, rB1, rB2, 0.f);
        __syncwarp();
        if (c + 1 < NCHUNK) {
            const float* nA = dApt + (size_t)(c + 1) * (CHUNK * 3);
            const float* nB = dBpt + (size_t)(c + 1) * (CHUNK * 3);
            rA0 = nA[hl * 3 + 0]; rA1 = nA[hl * 3 + 1]; rA2 = nA[hl * 3 + 2];
            rB0 = nB[hl * 3 + 0]; rB1 = nB[hl * 3 + 1]; rB2 = nB[hl * 3 + 2];
        }

#pragma unroll 1
        for (int tl = 0; tl < CHUNK; tl++) {
            const float4 dvA = *(const float4*)(&shd[0][h][tl * 4]);
            const float4 dvB = *(const float4*)(&shd[1][h][tl * 4]);

            // ================= STAGE 1 (A/B zipped) =================
            const float sA0 = SHF16(stvA, 0);
            const float sB0 = SHF16(stvB, 0);
            const float sA1 = SHF16(stvA, 8);
            const float sB1 = SHF16(stvB, 8);
            const float sA2 = SHF16(stvA, 4);
            const float sB2 = SHF16(stvB, 4);
            const float sA3 = SHF16(stvA, 12);
            const float sB3 = SHF16(stvB, 12);
            const float sA4 = SHF16(stvA, 2);
            const float sB4 = SHF16(stvB, 2);

            float aaA = b1a, acA = b1c, aaB = b1a, acB = b1c;
            aaA = fmaf(dvA.x, w1a[5], aaA); aaB = fmaf(dvB.x, w1a[5], aaB);
            acA = fmaf(dvA.x, w1b[5], acA); acB = fmaf(dvB.x, w1b[5], acB);
            aaA = fmaf(dvA.y, w1a[6], aaA); aaB = fmaf(dvB.y, w1a[6], aaB);
            acA = fmaf(dvA.y, w1b[6], acA); acB = fmaf(dvB.y, w1b[6], acB);
            aaA = fmaf(dvA.z, w1a[7], aaA); aaB = fmaf(dvB.z, w1a[7], aaB);
            acA = fmaf(dvA.z, w1b[7], acA); acB = fmaf(dvB.z, w1b[7], acB);
            aaA = fmaf(sA0, w1a[0], aaA);   aaB = fmaf(sB0, w1a[0], aaB);
            acA = fmaf(sA0, w1b[0], acA);   acB = fmaf(sB0, w1b[0], acB);
            aaA = fmaf(sA1, w1a[1], aaA);   aaB = fmaf(sB1, w1a[1], aaB);
            acA = fmaf(sA1, w1b[1], acA);   acB = fmaf(sB1, w1b[1], acB);
            aaA = fmaf(sA2, w1a[2], aaA);   aaB = fmaf(sB2, w1a[2], aaB);
            acA = fmaf(sA2, w1b[2], acA);   acB = fmaf(sB2, w1b[2], acB);
            aaA = fmaf(sA3, w1a[3], aaA);   aaB = fmaf(sB3, w1a[3], aaB);
            acA = fmaf(sA3, w1b[3], acA);   acB = fmaf(sB3, w1b[3], acB);
            aaA = fmaf(sA4, w1a[4], aaA);   aaB = fmaf(sB4, w1a[4], aaB);
            acA = fmaf(sA4, w1b[4], acA);   acB = fmaf(sB4, w1b[4], acB);

            *(float2*)(&lineA[j0]) = make_float2(tanh_hw(aaA), tanh_hw(acA));
            *(float2*)(&lineB[j0]) = make_float2(tanh_hw(aaB), tanh_hw(acB));
            __syncwarp();

            // ================= STAGE 2 (A/B zipped, 2 accums/channel) =========
            ulonglong2 uA = hpA[0], uB = hpB[0];
            ull aA0 = mul2(uA.x, w2p[0]);
            ull aB0 = mul2(uB.x, w2p[0]);
            ull aA1 = mul2(uA.y, w2p[1]);
            ull aB1 = mul2(uB.y, w2p[1]);
            ull cA0 = mul2(uA.x, w2q[0]);
            ull cB0 = mul2(uB.x, w2q[0]);
            ull cA1 = mul2(uA.y, w2q[1]);
            ull cB1 = mul2(uB.y, w2q[1]);
#pragma unroll
            for (int p = 1; p < 8; p++) {
                uA = hpA[p]; uB = hpB[p];
                fma2(aA0, uA.x, w2p[2 * p]);     fma2(aB0, uB.x, w2p[2 * p]);
                fma2(aA1, uA.y, w2p[2 * p + 1]); fma2(aB1, uB.y, w2p[2 * p + 1]);
                fma2(cA0, uA.x, w2q[2 * p]);     fma2(cB0, uB.x, w2q[2 * p]);
                fma2(cA1, uA.y, w2q[2 * p + 1]); fma2(cB1, uB.y, w2q[2 * p + 1]);
            }
            float lo, hi;
            unpack2(add2(aA0, aA1), lo, hi);
            const float yAa = lo + hi + b2a;
            unpack2(add2(aB0, aB1), lo, hi);
            const float yBa = lo + hi + b2a;
            unpack2(add2(cA0, cA1), lo, hi);
            const float yAc = lo + hi + b2c;
            unpack2(add2(cB0, cB1), lo, hi);
            const float yBc = lo + hi + b2c;
            const float h2aA = tanh_pre(yAa);
            const float h2aB = tanh_pre(yBa);
            const float h2cA = tanh_pre(yAc);
            const float h2cB = tanh_pre(yBc);

            // ================= STAGE 3 (products + zipped trees) ==============
            const float pA0 = fmaf(h2cA, w3b[0], h2aA * w3a[0]);
            const float pB0 = fmaf(h2cB, w3b[0], h2aB * w3a[0]);
            const float pA1 = fmaf(h2cA, w3b[1], h2aA * w3a[1]);
            const float pB1 = fmaf(h2cB, w3b[1], h2aB * w3a[1]);
            const float pA2 = fmaf(h2cA, w3b[2], h2aA * w3a[2]);
            const float pB2 = fmaf(h2cB, w3b[2], h2aB * w3a[2]);
            const float pA3 = fmaf(h2cA, w3b[3], h2aA * w3a[3]);
            const float pB3 = fmaf(h2cB, w3b[3], h2aB * w3a[3]);
            float       pA4 = fmaf(h2cA, w3b[4], h2aA * w3a[4]);
            float       pB4 = fmaf(h2cB, w3b[4], h2aB * w3a[4]);

            // round 1 (xor 8)
            float qA0  = t3 ? pA1 : pA0;
            float qA0u = t3 ? pA0 : pA1;
            float qB0  = t3 ? pB1 : pB0;
            float qB0u = t3 ? pB0 : pB1;
            qA0 += SHFX(qA0u, 8);
            qB0 += SHFX(qB0u, 8);
            float qA2  = t3 ? pA3 : pA2;
            float qA2u = t3 ? pA2 : pA3;
            float qB2  = t3 ? pB3 : pB2;
            float qB2u = t3 ? pB2 : pB3;
            qA2 += SHFX(qA2u, 8);
            qB2 += SHFX(qB2u, 8);
            pA4 += SHFX(pA4, 8);
            pB4 += SHFX(pB4, 8);
            // round 2 (xor 4)
            float cAv  = t2 ? qA2 : qA0;
            float cAu  = t2 ? qA0 : qA2;
            float cBv  = t2 ? qB2 : qB0;
            float cBu  = t2 ? qB0 : qB2;
            cAv += SHFX(cAu, 4);
            cBv += SHFX(cBu, 4);
            pA4 += SHFX(pA4, 4);
            pB4 += SHFX(pB4, 4);
            // round 3 (xor 2)
            float dA  = t1 ? pA4 : cAv;
            float dAu = t1 ? cAv : pA4;
            float dB  = t1 ? pB4 : cBv;
            float dBu = t1 ? cBv : pB4;
            dA += SHFX(dAu, 2);
            dB += SHFX(dBu, 2);
            // round 4 (xor 1)
            dA += SHFX(dA, 1);
            dB += SHFX(dB, 1);

            stvA += dA + b3v;
            stvB += dB + b3v;

            if (wr) { *oA = stvA; *oB = stvB; }
            oA += SDIM;
            oB += SDIM;
        }
    }
}

extern "C" void kernel_launch(void* const* d_in, const int* in_sizes, int n_in,
                              void* d_out, int out_size)
{
    const float* delta  = (const float*)d_in[0];
    const float* state0 = (const float*)d_in[1];
    const float* W1     = (const float*)d_in[2];
    const float* b1     = (const float*)d_in[3];
    const float* W2     = (const float*)d_in[4];
    const float* b2     = (const float*)d_in[5];
    const float* W3     = (const float*)d_in[6];
    const float* b3     = (const float*)d_in[7];
    float* out = (float*)d_out;

    dim3 grid(NBATCH / 4);   // 1024 one-warp blocks, 4 batches each
    dim3 block(32);
    msc_seq_kernel<<<grid, block>>>(delta, state0, W1, b1, W2, b2, W3, b3, out);
}